// round 4
// baseline (speedup 1.0000x reference)
#include <cuda_runtime.h>

// Shapes (fixed): x (1,384,256), gamma/beta (256), Wa/Wb (32,256),
// Wo (128,1024), bo (128) -> z (1,384,384,128) fp32
//
//   kA: layernorm(x) -> a = xn.Wa^T, b = xn.Wb^T          (384x32 each)
//   kB: U[i][o][d] = sum_c a[i][c] * Wo[o*1024 + c*32 + d] (384x128x32)
//   kC: z[i][j][o] = bo[o] + sum_d U[i][o][d] * b[j][d]
//
// kB/kC inner products use packed fma.rn.f32x2 (2 fp32 FMA per instruction;
// scalar FFMA only reaches half of Blackwell's fp32 peak).

#define L   384
#define DIM 256
#define H   32
#define OUT 128

typedef unsigned long long u64;

__device__ __forceinline__ u64 ffma2(u64 a, u64 b, u64 c) {
    u64 d;
    asm("fma.rn.f32x2 %0, %1, %2, %3;" : "=l"(d) : "l"(a), "l"(b), "l"(c));
    return d;
}
__device__ __forceinline__ u64 pack2(float lo, float hi) {
    u64 d;
    asm("mov.b64 %0, {%1, %2};" : "=l"(d) : "f"(lo), "f"(hi));
    return d;
}
__device__ __forceinline__ float2 unpack2(u64 v) {
    float2 r;
    asm("mov.b64 {%0, %1}, %2;" : "=f"(r.x), "=f"(r.y) : "l"(v));
    return r;
}

__device__ float g_U[L * OUT * H];   // 6.29 MB scratch, [i][o][d]
__device__ float g_a[L * H];         // [l][h]
__device__ float g_b[L * H];         // [l][h]

// ---------------------------------------------------------------------------
// Kernel A: layernorm + two 256-dot GEMVs per row. 384 blocks x 256 threads.
// Thread-quad per output: out = t>>2 (0..63), quad = t&3 covers 64 k's.
// Short dependency chains (4 accumulators + 2 shfls) instead of 8 serial
// full-warp reductions.
// ---------------------------------------------------------------------------
__global__ void __launch_bounds__(256) kA(
    const float* __restrict__ x, const float* __restrict__ gamma,
    const float* __restrict__ beta, const float* __restrict__ Wa,
    const float* __restrict__ Wb)
{
    const int l = blockIdx.x;
    const int t = threadIdx.x;
    const int lane = t & 31, w = t >> 5;

    __shared__ float xn_sh[DIM];
    __shared__ float red[16];
    __shared__ float mu_s, rstd_s;

    float v = x[l * DIM + t];

    float s = v, s2 = v * v;
    #pragma unroll
    for (int off = 16; off; off >>= 1) {
        s  += __shfl_down_sync(0xffffffffu, s,  off);
        s2 += __shfl_down_sync(0xffffffffu, s2, off);
    }
    if (lane == 0) { red[w] = s; red[8 + w] = s2; }
    __syncthreads();
    if (t == 0) {
        float S = 0.f, S2 = 0.f;
        #pragma unroll
        for (int k = 0; k < 8; k++) { S += red[k]; S2 += red[8 + k]; }
        float mu  = S * (1.0f / DIM);
        float var = S2 * (1.0f / DIM) - mu * mu;
        mu_s   = mu;
        rstd_s = rsqrtf(var + 1e-5f);
    }
    __syncthreads();

    xn_sh[t] = (v - mu_s) * rstd_s * gamma[t] + beta[t];
    __syncthreads();

    const int out  = t >> 2;        // 0..63: 0..31 -> a, 32..63 -> b
    const int quad = t & 3;
    const int h = out & 31;
    const float4* Wrow4 = (const float4*)((out < 32 ? Wa : Wb) + h * DIM) + quad * 16;
    const float4* xn4   = (const float4*)xn_sh + quad * 16;

    float a0 = 0.f, a1 = 0.f, a2 = 0.f, a3 = 0.f;
    #pragma unroll
    for (int m = 0; m < 16; m++) {
        float4 xv = xn4[m];
        float4 wv = Wrow4[m];
        a0 += xv.x * wv.x;
        a1 += xv.y * wv.y;
        a2 += xv.z * wv.z;
        a3 += xv.w * wv.w;
    }
    float acc = (a0 + a1) + (a2 + a3);
    acc += __shfl_xor_sync(0xffffffffu, acc, 1);
    acc += __shfl_xor_sync(0xffffffffu, acc, 2);
    if (quad == 0) {
        float* outp = (out < 32) ? g_a : g_b;
        outp[l * H + h] = acc;
    }
}

// ---------------------------------------------------------------------------
// Kernel B: U[i][o][d] = sum_c a[i][c] * Wo[o*1024 + c*32 + d]
// grid (48, 4): 8 i's per block, 32 o's per block. lane = d (coalesced).
// a stored transposed in smem ([c][i]) so i-pairs are contiguous for f32x2.
// ---------------------------------------------------------------------------
__global__ void __launch_bounds__(256) kB(const float* __restrict__ Wo)
{
    const int it0 = blockIdx.x * 8;
    const int oc  = blockIdx.y;
    const int t = threadIdx.x;
    const int lane = t & 31, w = t >> 5;

    __shared__ float a_sh[H * 8];   // [c][i]
    {
        int i = t >> 5, c = t & 31;
        a_sh[c * 8 + i] = g_a[(it0 + i) * H + c];
    }
    __syncthreads();

    #pragma unroll
    for (int p = 0; p < 4; p++) {
        const int o = oc * 32 + p * 8 + w;
        const float* wrow = Wo + o * (H * H) + lane;
        u64 acc2[4] = {0ull, 0ull, 0ull, 0ull};
        #pragma unroll
        for (int c = 0; c < H; c++) {
            float wv = wrow[c * H];
            u64 wv2 = pack2(wv, wv);
            const float2* ap = (const float2*)&a_sh[c * 8];
            #pragma unroll
            for (int ii = 0; ii < 4; ii++) {
                float2 av = ap[ii];
                acc2[ii] = ffma2(pack2(av.x, av.y), wv2, acc2[ii]);
            }
        }
        #pragma unroll
        for (int ii = 0; ii < 4; ii++) {
            float2 r = unpack2(acc2[ii]);
            g_U[((it0 + 2 * ii)     * OUT + o) * H + lane] = r.x;
            g_U[((it0 + 2 * ii + 1) * OUT + o) * H + lane] = r.y;
        }
    }
}

// ---------------------------------------------------------------------------
// Kernel C: z[i][j][o] = bo[o] + sum_d U[i][o][d] * b[j][d]
// grid (384, 6): one i, 64 j's per block. 256 threads = 8 warps.
// Thread: lane -> 4 o's (o = lane + 32*oo), warp -> 8 j's. 32 outputs/thread.
// Inner product over d done as 16 packed d-pairs via fma.rn.f32x2.
// U in smem with row stride 36 (conflict-free LDS.128); b reads broadcast.
// ---------------------------------------------------------------------------
#define USTRIDE 36
__global__ void __launch_bounds__(256) kC(
    const float* __restrict__ bo, float* __restrict__ z)
{
    const int i  = blockIdx.x;
    const int jt = blockIdx.y;
    const int t = threadIdx.x;
    const int lane = t & 31, w = t >> 5;

    __shared__ float U_sh[OUT * USTRIDE];  // 18432 B
    __shared__ float b_sh[64 * H];         // 8192 B

    // Load U[i] : 4096 floats = 1024 float4, pad-stride store
    {
        const float4* Ug4 = (const float4*)(g_U + i * (OUT * H));
        #pragma unroll
        for (int it = 0; it < 4; it++) {
            int idx = t + it * 256;
            int o = idx >> 3, d4 = idx & 7;
            float4 vv = Ug4[idx];
            *((float4*)&U_sh[o * USTRIDE + d4 * 4]) = vv;
        }
    }
    // Load b tile: 2048 floats = 512 float4
    {
        const float4* bg4 = (const float4*)(g_b + jt * 64 * H);
        #pragma unroll
        for (int it = 0; it < 2; it++) {
            int idx = t + it * 256;
            ((float4*)b_sh)[idx] = bg4[idx];
        }
    }
    __syncthreads();

    const int j0 = w * 8;

    u64 acc2[8][4];
    #pragma unroll
    for (int jj = 0; jj < 8; jj++)
        #pragma unroll
        for (int oo = 0; oo < 4; oo++) acc2[jj][oo] = 0ull;

    #pragma unroll 1
    for (int dc = 0; dc < H; dc += 8) {
        u64 u2[4][4];
        #pragma unroll
        for (int oo = 0; oo < 4; oo++) {
            float4 v0 = *((const float4*)&U_sh[(lane + 32 * oo) * USTRIDE + dc]);
            float4 v1 = *((const float4*)&U_sh[(lane + 32 * oo) * USTRIDE + dc + 4]);
            u2[oo][0] = pack2(v0.x, v0.y);
            u2[oo][1] = pack2(v0.z, v0.w);
            u2[oo][2] = pack2(v1.x, v1.y);
            u2[oo][3] = pack2(v1.z, v1.w);
        }
        #pragma unroll
        for (int jj = 0; jj < 8; jj++) {
            float4 w0 = *((const float4*)&b_sh[(j0 + jj) * H + dc]);
            float4 w1 = *((const float4*)&b_sh[(j0 + jj) * H + dc + 4]);
            u64 b2[4];
            b2[0] = pack2(w0.x, w0.y);
            b2[1] = pack2(w0.z, w0.w);
            b2[2] = pack2(w1.x, w1.y);
            b2[3] = pack2(w1.z, w1.w);
            #pragma unroll
            for (int oo = 0; oo < 4; oo++)
                #pragma unroll
                for (int k = 0; k < 4; k++)
                    acc2[jj][oo] = ffma2(u2[oo][k], b2[k], acc2[jj][oo]);
        }
    }

    float bov[4];
    #pragma unroll
    for (int oo = 0; oo < 4; oo++) bov[oo] = bo[lane + 32 * oo];

    long base = ((long)(i * L + jt * 64 + j0)) * OUT;
    #pragma unroll
    for (int jj = 0; jj < 8; jj++) {
        float* zp = z + base + (long)jj * OUT + lane;
        #pragma unroll
        for (int oo = 0; oo < 4; oo++) {
            float2 r = unpack2(acc2[jj][oo]);
            zp[32 * oo] = (r.x + r.y) + bov[oo];
        }
    }
}

// ---------------------------------------------------------------------------
extern "C" void kernel_launch(void* const* d_in, const int* in_sizes, int n_in,
                              void* d_out, int out_size)
{
    const float* x     = (const float*)d_in[0];
    const float* gamma = (const float*)d_in[1];
    const float* beta  = (const float*)d_in[2];
    const float* Wa    = (const float*)d_in[3];
    const float* Wb    = (const float*)d_in[4];
    const float* Wo    = (const float*)d_in[5];
    const float* bo    = (const float*)d_in[6];
    float* z = (float*)d_out;

    kA<<<L, 256>>>(x, gamma, beta, Wa, Wb);
    kB<<<dim3(48, 4), 256>>>(Wo);
    kC<<<dim3(L, 6), 256>>>(bo, z);
}